// round 14
// baseline (speedup 1.0000x reference)
#include <cuda_runtime.h>
#include <cstdint>

// Problem constants
#define B_ 4
#define N_ 1024
#define H_ 256
#define D_ 32
#define M_ (B_ * N_)              // 4096 token rows
#define OUT_PER_B (D_ * D_ * H_)  // 262144

// Scratch (device globals — no allocation allowed)
__device__ float g_k0[M_ * D_];        // [b][n][d]
__device__ float g_v0[M_ * D_];        // [b][n][d]
__device__ float g_dk[M_ * D_];        // [b][n][d]
__device__ float g_khF[B_ * N_ * H_];  // [b][n][h]
__device__ float g_vhF[B_ * N_ * H_];  // [b][n][h]
__device__ float g_dhF[B_ * N_ * H_];  // [b][n][h]

// ---- packed f32x2 helpers (sm_103a FFMA2 path) ----
typedef unsigned long long ull;
__device__ __forceinline__ ull pack2(float lo, float hi) {
    ull r; asm("mov.b64 %0, {%1, %2};" : "=l"(r) : "f"(lo), "f"(hi)); return r;
}
__device__ __forceinline__ void unpack2(float& lo, float& hi, ull v) {
    asm("mov.b64 {%0, %1}, %2;" : "=f"(lo), "=f"(hi) : "l"(v));
}
__device__ __forceinline__ void fma2(ull& d, ull a, ull b) {
    asm("fma.rn.f32x2 %0, %1, %2, %3;" : "=l"(d) : "l"(a), "l"(b), "l"(d));
}

// ---- cp.async (LDGSTS) helpers ----
__device__ __forceinline__ void cpa16(unsigned int dst, const float* src) {
    asm volatile("cp.async.ca.shared.global [%0], [%1], 16;" :: "r"(dst), "l"(src));
}
__device__ __forceinline__ void cpa_commit() {
    asm volatile("cp.async.commit_group;" ::: "memory");
}
template <int N>
__device__ __forceinline__ void cpa_wait() {
    asm volatile("cp.async.wait_group %0;" :: "n"(N) : "memory");
}

// ---- fast activations: 1 MUFU each via tanh.approx ----
__device__ __forceinline__ float tanhfast(float x) {
    float y; asm("tanh.approx.f32 %0, %1;" : "=f"(y) : "f"(x)); return y;
}
__device__ __forceinline__ float sigf(float x) {
    return fmaf(tanhfast(0.5f * x), 0.5f, 0.5f);
}
__device__ __forceinline__ float siluf(float x) {
    float h = 0.5f * x;
    return fmaf(h, tanhfast(h), h);
}

__device__ __forceinline__ void route32(int cbase,
    const float* Wkv, const float* Wkvh, const float* Wd, const float* Wdh,
    const float*& Wp, int& width, int& coff)
{
    if (cbase < 64)       { Wp = Wkv;  width = 64;  coff = cbase;       }
    else if (cbase < 576) { Wp = Wkvh; width = 512; coff = cbase - 64;  }
    else if (cbase < 608) { Wp = Wd;   width = 32;  coff = cbase - 576; }
    else                  { Wp = Wdh;  width = 256; coff = cbase - 608; }
}

// ---------------------------------------------------------------------------
// Pass 1: projection GEMM, FFMA2, tile 128m x 48e, 256 threads, microtile
// 4m (stride-32 rows: conflict-free vs R11's 2-way A-read conflict) x 6e.
// cp.async double-buffered. 576 blocks, 4 blocks/SM = 8 warps/SMSP (2x the
// latency cover of the 128-thread version at identical port time).
// ---------------------------------------------------------------------------
__global__ __launch_bounds__(256, 4) void proj_kernel(
    const float* __restrict__ token,
    const float* __restrict__ Wkv,
    const float* __restrict__ Wkvh,
    const float* __restrict__ Wd,
    const float* __restrict__ Wdh)
{
    __shared__ __align__(16) float As[2][128][36];  // 36KB
    __shared__ __align__(16) float Bs[2][32][48];   // 12KB (total 48KB)

    const int tid = threadIdx.x;
    const int tn = tid & 7;     // e-group: cols tn*6..+5
    const int tm2 = tid >> 3;   // m rows: tm2 + 32*i, i=0..3
    const int m0 = blockIdx.y * 128;
    const int n0 = blockIdx.x * 48;

    const unsigned int sA = (unsigned int)__cvta_generic_to_shared(&As[0][0][0]);
    const unsigned int sB = (unsigned int)__cvta_generic_to_shared(&Bs[0][0][0]);

    // async-load k-tile kt into buffer buf.
    // A: 1024 16B chunks / 256 thr = 4 each (rows tm2 + 32*i, cols tn*4).
    // B: 384 4-float chunks; thread handles cid = tid and (tid<128) cid=256+tid.
    //    Region boundaries are multiples of 4 so each chunk is one matrix.
    auto load_tile = [&](int kt, int buf) {
        #pragma unroll
        for (int i = 0; i < 4; i++) {
            int row = tm2 + 32 * i;
            cpa16(sA + (unsigned int)((buf * 128 + row) * 36 + tn * 4) * 4u,
                  &token[(size_t)(m0 + row) * 256 + kt + tn * 4]);
        }
        #pragma unroll
        for (int s = 0; s < 2; s++) {
            int cid = tid + 256 * s;
            if (cid < 384) {
                int k = cid / 12;
                int g = cid % 12;
                const float* Wp; int width, coff;
                route32(n0 + g * 4, Wkv, Wkvh, Wd, Wdh, Wp, width, coff);
                cpa16(sB + (unsigned int)((buf * 32 + k) * 48 + g * 4) * 4u,
                      &Wp[(size_t)(kt + k) * width + coff]);
            }
        }
        cpa_commit();
    };

    load_tile(0, 0);

    // acc[i][q]: m row tm2 + 32*i, e-pair q (e = tn*6 + 2q, +1)
    ull acc[4][3];
    #pragma unroll
    for (int i = 0; i < 4; i++)
        #pragma unroll
        for (int q = 0; q < 3; q++) acc[i][q] = 0ull;

    for (int it = 0; it < 8; it++) {
        const int p = it & 1;
        if (it < 7) {
            load_tile((it + 1) * 32, p ^ 1);
            cpa_wait<1>();
        } else {
            cpa_wait<0>();
        }
        __syncthreads();

        #pragma unroll
        for (int kk4 = 0; kk4 < 8; kk4++) {
            float4 a4[4];
            #pragma unroll
            for (int i = 0; i < 4; i++)
                a4[i] = *reinterpret_cast<const float4*>(&As[p][tm2 + 32 * i][kk4 * 4]);
            #pragma unroll
            for (int u = 0; u < 4; u++) {
                const int kk = kk4 * 4 + u;
                ull b0 = *reinterpret_cast<const ull*>(&Bs[p][kk][tn * 6]);
                ull b1 = *reinterpret_cast<const ull*>(&Bs[p][kk][tn * 6 + 2]);
                ull b2 = *reinterpret_cast<const ull*>(&Bs[p][kk][tn * 6 + 4]);
                #pragma unroll
                for (int i = 0; i < 4; i++) {
                    float av = (u == 0) ? a4[i].x : (u == 1) ? a4[i].y
                             : (u == 2) ? a4[i].z : a4[i].w;
                    ull ad = pack2(av, av);
                    fma2(acc[i][0], ad, b0);
                    fma2(acc[i][1], ad, b1);
                    fma2(acc[i][2], ad, b2);
                }
            }
        }

        if (it < 6) __syncthreads();
    }

    // Epilogue: route each e-pair (boundaries are even); store float2
    #pragma unroll
    for (int q = 0; q < 3; q++) {
        const int ch = n0 + tn * 6 + q * 2;
        float* bp; int stride, off;
        if (ch < 32)       { bp = g_k0;  stride = 32;  off = ch; }
        else if (ch < 64)  { bp = g_v0;  stride = 32;  off = ch - 32; }
        else if (ch < 320) { bp = g_khF; stride = 256; off = ch - 64; }
        else if (ch < 576) { bp = g_vhF; stride = 256; off = ch - 320; }
        else if (ch < 608) { bp = g_dk;  stride = 32;  off = ch - 576; }
        else               { bp = g_dhF; stride = 256; off = ch - 608; }
        #pragma unroll
        for (int i = 0; i < 4; i++) {
            int m = m0 + tm2 + 32 * i;
            float lo, hi;
            unpack2(lo, hi, acc[i][q]);
            *reinterpret_cast<float2*>(&bp[(size_t)m * stride + off]) =
                make_float2(lo, hi);
        }
    }
}

// ---------------------------------------------------------------------------
// Pass 2: block per (b,h), 256 threads, 4 blocks/SM. Tile of 64 n.
// (Measured 31.2-32.1us five times; unchanged.)
// ---------------------------------------------------------------------------
#define TT 64
#define NT (N_ / TT)
#define OFF_SV   0                    // [2][64][36] = 4608
#define OFF_SK   4608                 // [64][36]    = 2304
#define OFF_SIG  6912                 // [64][33]    = 2112
#define OFF_PROD 9024                 // [8][32]     = 256
#define OFF_CAR  9280                 // [2][32]     = 64
#define SMEM_FLOATS 9344

__global__ __launch_bounds__(256, 4) void accum_kernel(float* __restrict__ out)
{
    __shared__ __align__(16) float sm[SMEM_FLOATS];
    float* sV   = sm + OFF_SV;
    float* sK   = sm + OFF_SK;
    float* sSig = sm + OFF_SIG;
    float* sPr  = sm + OFF_PROD;
    float* sCar = sm + OFF_CAR;

    const int tid = threadIdx.x;
    const int bh = blockIdx.x;
    const int b = bh >> 8;
    const int h = bh & 255;

    const float* __restrict__ dk = g_dk + b * (N_ * D_);
    const float* __restrict__ k0 = g_k0 + b * (N_ * D_);
    const float* __restrict__ v0 = g_v0 + b * (N_ * D_);
    const float* __restrict__ khp = g_khF + (size_t)b * (N_ * H_) + h;
    const float* __restrict__ vhp = g_vhF + (size_t)b * (N_ * H_) + h;
    const float* __restrict__ dhp = g_dhF + (size_t)b * (N_ * H_) + h;

    const int c = tid >> 5, d = tid & 31;
    const int js = tid >> 6;
    const int td = (tid >> 3) & 7;
    const int te = tid & 7;

    if (tid < 64) sCar[tid] = 1.f;
    __syncthreads();

    ull acc[2][4];
    #pragma unroll
    for (int i = 0; i < 2; i++)
        #pragma unroll
        for (int q = 0; q < 4; q++) acc[i][q] = 0ull;

    float kreg[8];
    int tprod = NT;

    auto do_c = [&](int pv) {
        #pragma unroll
        for (int jj = 0; jj < 16; jj++) {
            int j = jj * 4 + js;
            ulonglong2 kq = *reinterpret_cast<const ulonglong2*>(&sK[j * 36 + td * 4]);
            float4 vq = *reinterpret_cast<const float4*>(&sV[pv * 2304 + j * 36 + te * 4]);
            ull vd0 = pack2(vq.x, vq.x);
            ull vd1 = pack2(vq.y, vq.y);
            ull vd2 = pack2(vq.z, vq.z);
            ull vd3 = pack2(vq.w, vq.w);
            fma2(acc[0][0], kq.x, vd0);
            fma2(acc[0][1], kq.x, vd1);
            fma2(acc[0][2], kq.x, vd2);
            fma2(acc[0][3], kq.x, vd3);
            fma2(acc[1][0], kq.y, vd0);
            fma2(acc[1][1], kq.y, vd1);
            fma2(acc[1][2], kq.y, vd2);
            fma2(acc[1][3], kq.y, vd3);
        }
    };

    for (int t = 0; t < NT; t++) {
        const int pb = t & 1;

        float p = 1.f;
        #pragma unroll
        for (int jj = 0; jj < 8; jj++) {
            int j = c * 8 + jj;
            int n = t * TT + j;
            float s = 1.f;
            if (n) {
                int mm = N_ - n;
                s = sigf(dk[mm * D_ + d] * dhp[(size_t)mm << 8]);
            }
            p *= s;
            sSig[j * 33 + d] = s;
            kreg[jj] = siluf(k0[n * D_ + d] * khp[(size_t)n << 8]);
            sV[pb * 2304 + j * 36 + d] = siluf(v0[n * D_ + d] * vhp[(size_t)n << 8]);
        }
        sPr[c * 32 + d] = p;

        if (t) do_c(pb ^ 1);
        __syncthreads();

        float p2 = sCar[pb * 32 + d];
        #pragma unroll
        for (int cc = 0; cc < 7; cc++)
            if (cc < c) p2 *= sPr[cc * 32 + d];
        #pragma unroll
        for (int jj = 0; jj < 8; jj++) {
            int j = c * 8 + jj;
            p2 *= sSig[j * 33 + d];
            sK[j * 36 + d] = kreg[jj] * p2;
        }
        bool alivep = false;
        if (c == 7) {
            sCar[(pb ^ 1) * 32 + d] = p2;
            alivep = (p2 != 0.f);
        }
        if (!__syncthreads_or(alivep)) { tprod = t + 1; break; }
    }

    do_c((tprod - 1) & 1);
    __syncthreads();

    float* red = sm;
    #pragma unroll
    for (int i = 0; i < 2; i++)
        #pragma unroll
        for (int q = 0; q < 4; q++) {
            float lo, hi;
            unpack2(lo, hi, acc[i][q]);
            int e = te * 4 + q;
            red[js * 1024 + (td * 4 + 2 * i) * 32 + e]     = lo;
            red[js * 1024 + (td * 4 + 2 * i + 1) * 32 + e] = hi;
        }
    __syncthreads();

    float4 r0 = *reinterpret_cast<const float4*>(&red[tid * 4]);
    float4 r1 = *reinterpret_cast<const float4*>(&red[1024 + tid * 4]);
    float4 r2 = *reinterpret_cast<const float4*>(&red[2048 + tid * 4]);
    float4 r3 = *reinterpret_cast<const float4*>(&red[3072 + tid * 4]);
    float o0 = (r0.x + r1.x) + (r2.x + r3.x);
    float o1 = (r0.y + r1.y) + (r2.y + r3.y);
    float o2 = (r0.z + r1.z) + (r2.z + r3.z);
    float o3 = (r0.w + r1.w) + (r2.w + r3.w);

    float* op = out + (size_t)b * OUT_PER_B + (size_t)(tid * 4) * 256 + h;
    op[0]   = o0;
    op[256] = o1;
    op[512] = o2;
    op[768] = o3;
}

extern "C" void kernel_launch(void* const* d_in, const int* in_sizes, int n_in,
                              void* d_out, int out_size) {
    (void)in_sizes; (void)n_in; (void)out_size;
    const float* token = (const float*)d_in[0];
    const float* Wkv   = (const float*)d_in[1];
    const float* Wkvh  = (const float*)d_in[2];
    const float* Wd    = (const float*)d_in[3];
    const float* Wdh   = (const float*)d_in[4];

    proj_kernel<<<dim3(18, 32), 256>>>(token, Wkv, Wkvh, Wd, Wdh);
    accum_kernel<<<dim3(B_ * H_), 256>>>((float*)d_out);
}

// round 15
// speedup vs baseline: 1.0745x; 1.0745x over previous
#include <cuda_runtime.h>
#include <cstdint>

// Problem constants
#define B_ 4
#define N_ 1024
#define H_ 256
#define D_ 32
#define M_ (B_ * N_)              // 4096 token rows
#define OUT_PER_B (D_ * D_ * H_)  // 262144

// Scratch (device globals — no allocation allowed)
__device__ float g_k0[M_ * D_];        // [b][n][d]
__device__ float g_v0[M_ * D_];        // [b][n][d]
__device__ float g_dk[M_ * D_];        // [b][n][d]
__device__ float g_khF[B_ * N_ * H_];  // [b][n][h]
__device__ float g_vhF[B_ * N_ * H_];  // [b][n][h]
__device__ float g_dhF[B_ * N_ * H_];  // [b][n][h]

// ---- packed f32x2 helpers (sm_103a FFMA2 path) ----
typedef unsigned long long ull;
__device__ __forceinline__ ull pack2(float lo, float hi) {
    ull r; asm("mov.b64 %0, {%1, %2};" : "=l"(r) : "f"(lo), "f"(hi)); return r;
}
__device__ __forceinline__ void unpack2(float& lo, float& hi, ull v) {
    asm("mov.b64 {%0, %1}, %2;" : "=f"(lo), "=f"(hi) : "l"(v));
}
__device__ __forceinline__ void fma2(ull& d, ull a, ull b) {
    asm("fma.rn.f32x2 %0, %1, %2, %3;" : "=l"(d) : "l"(a), "l"(b), "l"(d));
}

// ---- cp.async (LDGSTS) helpers; .cg = L2-only, data consumed via smem ----
__device__ __forceinline__ void cpa16(unsigned int dst, const float* src) {
    asm volatile("cp.async.cg.shared.global [%0], [%1], 16;" :: "r"(dst), "l"(src));
}
__device__ __forceinline__ void cpa_commit() {
    asm volatile("cp.async.commit_group;" ::: "memory");
}
template <int N>
__device__ __forceinline__ void cpa_wait() {
    asm volatile("cp.async.wait_group %0;" :: "n"(N) : "memory");
}

// ---- fast activations: 1 MUFU each via tanh.approx ----
__device__ __forceinline__ float tanhfast(float x) {
    float y; asm("tanh.approx.f32 %0, %1;" : "=f"(y) : "f"(x)); return y;
}
__device__ __forceinline__ float sigf(float x) {
    return fmaf(tanhfast(0.5f * x), 0.5f, 0.5f);
}
__device__ __forceinline__ float siluf(float x) {
    float h = 0.5f * x;
    return fmaf(h, tanhfast(h), h);
}

__device__ __forceinline__ void route32(int cbase,
    const float* Wkv, const float* Wkvh, const float* Wd, const float* Wdh,
    const float*& Wp, int& width, int& coff)
{
    if (cbase < 64)       { Wp = Wkv;  width = 64;  coff = cbase;       }
    else if (cbase < 576) { Wp = Wkvh; width = 512; coff = cbase - 64;  }
    else if (cbase < 608) { Wp = Wd;   width = 32;  coff = cbase - 576; }
    else                  { Wp = Wdh;  width = 256; coff = cbase - 608; }
}

// ---------------------------------------------------------------------------
// Pass 1: projection GEMM, FFMA2, tile 128m x 48e, 128 threads, microtile
// 8m (stride-16 rows) x 6e. cp.async double-buffered pipeline.
// 864/48 x 32 = 576 blocks -> exactly 4 blocks/SM in ONE balanced wave.
// (R11 kernel — measured 41us / 72.2us total, the session best.)
// ---------------------------------------------------------------------------
__global__ __launch_bounds__(128, 4) void proj_kernel(
    const float* __restrict__ token,
    const float* __restrict__ Wkv,
    const float* __restrict__ Wkvh,
    const float* __restrict__ Wd,
    const float* __restrict__ Wdh)
{
    __shared__ __align__(16) float As[2][128][36];  // 36KB
    __shared__ __align__(16) float Bs[2][32][48];   // 12KB (total 48KB)

    const int tid = threadIdx.x;
    const int tn = tid & 7;    // e-group: cols tn*6..+5
    const int tm = tid >> 3;   // m rows: tm + 16*i, i=0..7
    const int m0 = blockIdx.y * 128;
    const int n0 = blockIdx.x * 48;

    // B loader routing: 3 chunks per thread; chunk cid = tid + 128*s covers
    // k = cid/12, cols g*4..g*4+3 (g = cid%12). Region boundaries are
    // multiples of 4, so each 4-col chunk lies in one matrix.
    const float* Wrow[3]; int Ww[3]; int Wk[3]; int Wg[3];
    #pragma unroll
    for (int s = 0; s < 3; s++) {
        int cid = tid + 128 * s;
        Wk[s] = cid / 12;
        Wg[s] = cid % 12;
        const float* Wp; int width, coff;
        route32(n0 + Wg[s] * 4, Wkv, Wkvh, Wd, Wdh, Wp, width, coff);
        Wrow[s] = Wp + coff;
        Ww[s] = width;
    }

    const unsigned int sA = (unsigned int)__cvta_generic_to_shared(&As[0][0][0]);
    const unsigned int sB = (unsigned int)__cvta_generic_to_shared(&Bs[0][0][0]);

    auto load_tile = [&](int kt, int buf) {
        #pragma unroll
        for (int pp = 0; pp < 8; pp++) {
            int row = pp * 16 + tm;
            cpa16(sA + (unsigned int)((buf * 128 + row) * 36 + tn * 4) * 4u,
                  &token[(size_t)(m0 + row) * 256 + kt + tn * 4]);
        }
        #pragma unroll
        for (int s = 0; s < 3; s++) {
            cpa16(sB + (unsigned int)((buf * 32 + Wk[s]) * 48 + Wg[s] * 4) * 4u,
                  Wrow[s] + (size_t)(kt + Wk[s]) * Ww[s]);
        }
        cpa_commit();
    };

    load_tile(0, 0);

    // acc[i][q]: m row tm+16i, e-pair q (e = tn*6 + 2q, +1)
    ull acc[8][3];
    #pragma unroll
    for (int i = 0; i < 8; i++)
        #pragma unroll
        for (int q = 0; q < 3; q++) acc[i][q] = 0ull;

    for (int it = 0; it < 8; it++) {
        const int p = it & 1;
        if (it < 7) {
            load_tile((it + 1) * 32, p ^ 1);
            cpa_wait<1>();
        } else {
            cpa_wait<0>();
        }
        __syncthreads();

        #pragma unroll
        for (int kk4 = 0; kk4 < 8; kk4++) {
            float4 a4[8];
            #pragma unroll
            for (int i = 0; i < 8; i++)
                a4[i] = *reinterpret_cast<const float4*>(&As[p][tm + 16 * i][kk4 * 4]);
            #pragma unroll
            for (int u = 0; u < 4; u++) {
                const int kk = kk4 * 4 + u;
                ull b0 = *reinterpret_cast<const ull*>(&Bs[p][kk][tn * 6]);
                ull b1 = *reinterpret_cast<const ull*>(&Bs[p][kk][tn * 6 + 2]);
                ull b2 = *reinterpret_cast<const ull*>(&Bs[p][kk][tn * 6 + 4]);
                #pragma unroll
                for (int i = 0; i < 8; i++) {
                    float av = (u == 0) ? a4[i].x : (u == 1) ? a4[i].y
                             : (u == 2) ? a4[i].z : a4[i].w;
                    ull ad = pack2(av, av);
                    fma2(acc[i][0], ad, b0);
                    fma2(acc[i][1], ad, b1);
                    fma2(acc[i][2], ad, b2);
                }
            }
        }

        if (it < 6) __syncthreads();
    }

    // Epilogue: route each e-pair (boundaries are even); store float2
    #pragma unroll
    for (int q = 0; q < 3; q++) {
        const int ch = n0 + tn * 6 + q * 2;
        float* bp; int stride, off;
        if (ch < 32)       { bp = g_k0;  stride = 32;  off = ch; }
        else if (ch < 64)  { bp = g_v0;  stride = 32;  off = ch - 32; }
        else if (ch < 320) { bp = g_khF; stride = 256; off = ch - 64; }
        else if (ch < 576) { bp = g_vhF; stride = 256; off = ch - 320; }
        else if (ch < 608) { bp = g_dk;  stride = 32;  off = ch - 576; }
        else               { bp = g_dhF; stride = 256; off = ch - 608; }
        #pragma unroll
        for (int i = 0; i < 8; i++) {
            int m = m0 + tm + 16 * i;
            float lo, hi;
            unpack2(lo, hi, acc[i][q]);
            *reinterpret_cast<float2*>(&bp[(size_t)m * stride + off]) =
                make_float2(lo, hi);
        }
    }
}

// ---------------------------------------------------------------------------
// Pass 2: block per (b,h), 256 threads, 4 blocks/SM. Tile of 64 n.
// A1: all gmem loads + activations, overlapped with phase C(t-1) FMAs.
// A2B: prefix-product chain + K stores. Early exit on weight underflow.
// (Measured 31.2-32.1us six times; unchanged.)
// ---------------------------------------------------------------------------
#define TT 64
#define NT (N_ / TT)
#define OFF_SV   0                    // [2][64][36] = 4608
#define OFF_SK   4608                 // [64][36]    = 2304
#define OFF_SIG  6912                 // [64][33]    = 2112
#define OFF_PROD 9024                 // [8][32]     = 256
#define OFF_CAR  9280                 // [2][32]     = 64
#define SMEM_FLOATS 9344

__global__ __launch_bounds__(256, 4) void accum_kernel(float* __restrict__ out)
{
    __shared__ __align__(16) float sm[SMEM_FLOATS];
    float* sV   = sm + OFF_SV;
    float* sK   = sm + OFF_SK;
    float* sSig = sm + OFF_SIG;
    float* sPr  = sm + OFF_PROD;
    float* sCar = sm + OFF_CAR;

    const int tid = threadIdx.x;
    const int bh = blockIdx.x;
    const int b = bh >> 8;
    const int h = bh & 255;

    const float* __restrict__ dk = g_dk + b * (N_ * D_);
    const float* __restrict__ k0 = g_k0 + b * (N_ * D_);
    const float* __restrict__ v0 = g_v0 + b * (N_ * D_);
    const float* __restrict__ khp = g_khF + (size_t)b * (N_ * H_) + h;
    const float* __restrict__ vhp = g_vhF + (size_t)b * (N_ * H_) + h;
    const float* __restrict__ dhp = g_dhF + (size_t)b * (N_ * H_) + h;

    const int c = tid >> 5, d = tid & 31;
    const int js = tid >> 6;
    const int td = (tid >> 3) & 7;
    const int te = tid & 7;

    if (tid < 64) sCar[tid] = 1.f;
    __syncthreads();

    ull acc[2][4];
    #pragma unroll
    for (int i = 0; i < 2; i++)
        #pragma unroll
        for (int q = 0; q < 4; q++) acc[i][q] = 0ull;

    float kreg[8];
    int tprod = NT;

    auto do_c = [&](int pv) {
        #pragma unroll
        for (int jj = 0; jj < 16; jj++) {
            int j = jj * 4 + js;
            ulonglong2 kq = *reinterpret_cast<const ulonglong2*>(&sK[j * 36 + td * 4]);
            float4 vq = *reinterpret_cast<const float4*>(&sV[pv * 2304 + j * 36 + te * 4]);
            ull vd0 = pack2(vq.x, vq.x);
            ull vd1 = pack2(vq.y, vq.y);
            ull vd2 = pack2(vq.z, vq.z);
            ull vd3 = pack2(vq.w, vq.w);
            fma2(acc[0][0], kq.x, vd0);
            fma2(acc[0][1], kq.x, vd1);
            fma2(acc[0][2], kq.x, vd2);
            fma2(acc[0][3], kq.x, vd3);
            fma2(acc[1][0], kq.y, vd0);
            fma2(acc[1][1], kq.y, vd1);
            fma2(acc[1][2], kq.y, vd2);
            fma2(acc[1][3], kq.y, vd3);
        }
    };

    for (int t = 0; t < NT; t++) {
        const int pb = t & 1;

        float p = 1.f;
        #pragma unroll
        for (int jj = 0; jj < 8; jj++) {
            int j = c * 8 + jj;
            int n = t * TT + j;
            float s = 1.f;
            if (n) {
                int mm = N_ - n;
                s = sigf(dk[mm * D_ + d] * dhp[(size_t)mm << 8]);
            }
            p *= s;
            sSig[j * 33 + d] = s;
            kreg[jj] = siluf(k0[n * D_ + d] * khp[(size_t)n << 8]);
            sV[pb * 2304 + j * 36 + d] = siluf(v0[n * D_ + d] * vhp[(size_t)n << 8]);
        }
        sPr[c * 32 + d] = p;

        if (t) do_c(pb ^ 1);
        __syncthreads();

        float p2 = sCar[pb * 32 + d];
        #pragma unroll
        for (int cc = 0; cc < 7; cc++)
            if (cc < c) p2 *= sPr[cc * 32 + d];
        #pragma unroll
        for (int jj = 0; jj < 8; jj++) {
            int j = c * 8 + jj;
            p2 *= sSig[j * 33 + d];
            sK[j * 36 + d] = kreg[jj] * p2;
        }
        bool alivep = false;
        if (c == 7) {
            sCar[(pb ^ 1) * 32 + d] = p2;
            alivep = (p2 != 0.f);
        }
        if (!__syncthreads_or(alivep)) { tprod = t + 1; break; }
    }

    do_c((tprod - 1) & 1);
    __syncthreads();

    float* red = sm;
    #pragma unroll
    for (int i = 0; i < 2; i++)
        #pragma unroll
        for (int q = 0; q < 4; q++) {
            float lo, hi;
            unpack2(lo, hi, acc[i][q]);
            int e = te * 4 + q;
            red[js * 1024 + (td * 4 + 2 * i) * 32 + e]     = lo;
            red[js * 1024 + (td * 4 + 2 * i + 1) * 32 + e] = hi;
        }
    __syncthreads();

    float4 r0 = *reinterpret_cast<const float4*>(&red[tid * 4]);
    float4 r1 = *reinterpret_cast<const float4*>(&red[1024 + tid * 4]);
    float4 r2 = *reinterpret_cast<const float4*>(&red[2048 + tid * 4]);
    float4 r3 = *reinterpret_cast<const float4*>(&red[3072 + tid * 4]);
    float o0 = (r0.x + r1.x) + (r2.x + r3.x);
    float o1 = (r0.y + r1.y) + (r2.y + r3.y);
    float o2 = (r0.z + r1.z) + (r2.z + r3.z);
    float o3 = (r0.w + r1.w) + (r2.w + r3.w);

    float* op = out + (size_t)b * OUT_PER_B + (size_t)(tid * 4) * 256 + h;
    op[0]   = o0;
    op[256] = o1;
    op[512] = o2;
    op[768] = o3;
}

extern "C" void kernel_launch(void* const* d_in, const int* in_sizes, int n_in,
                              void* d_out, int out_size) {
    (void)in_sizes; (void)n_in; (void)out_size;
    const float* token = (const float*)d_in[0];
    const float* Wkv   = (const float*)d_in[1];
    const float* Wkvh  = (const float*)d_in[2];
    const float* Wd    = (const float*)d_in[3];
    const float* Wdh   = (const float*)d_in[4];

    proj_kernel<<<dim3(18, 32), 128>>>(token, Wkv, Wkvh, Wd, Wdh);
    accum_kernel<<<dim3(B_ * H_), 256>>>((float*)d_out);
}